// round 3
// baseline (speedup 1.0000x reference)
#include <cuda_runtime.h>
#include <cuda_bf16.h>
#include <math.h>
#include <stdint.h>

#define BB 2
#define SS 2048
#define NH 16
#define HD 128
#define MR (BB*SS)   // 4096 rows

// ---------------- scratch (static device globals; no allocation) ----------------
__device__ float g_comp[MR*512];
__device__ float g_qr[MR*1024];
__device__ float g_kr[MR*1024];
__device__ float g_qn[MR*1024];
__device__ float g_kn[MR*1024];
__device__ float g_vf[MR*2048];
__device__ float g_Q[(size_t)BB*NH*SS*HD];
__device__ float g_K[(size_t)BB*NH*SS*HD];
__device__ float g_V[(size_t)BB*NH*SS*HD];
__device__ float g_ctx[(size_t)MR*2048];

// ---------------- bf16-split helpers ----------------
// pack two consecutive-k floats into (hi bf16x2, lo bf16x2) where lo = x - hi.
__device__ __forceinline__ void split2(float f0, float f1, uint32_t& hi, uint32_t& lo) {
    __nv_bfloat162 h = __floats2bfloat162_rn(f0, f1);
    float r0 = f0 - __bfloat162float(h.x);
    float r1 = f1 - __bfloat162float(h.y);
    __nv_bfloat162 l = __floats2bfloat162_rn(r0, r1);
    hi = *reinterpret_cast<uint32_t*>(&h);
    lo = *reinterpret_cast<uint32_t*>(&l);
}

// m16n8k16 row.col bf16 mma, fp32 accumulate in place.
__device__ __forceinline__ void mma16(float* c, const uint32_t* a, const uint32_t* b) {
    asm volatile(
        "mma.sync.aligned.m16n8k16.row.col.f32.bf16.bf16.f32 "
        "{%0,%1,%2,%3},{%4,%5,%6,%7},{%8,%9},{%0,%1,%2,%3};"
        : "+f"(c[0]), "+f"(c[1]), "+f"(c[2]), "+f"(c[3])
        : "r"(a[0]), "r"(a[1]), "r"(a[2]), "r"(a[3]), "r"(b[0]), "r"(b[1]));
}

// ---------------- GEMM: C[M,N] = A[M,K] @ B[K,N], bf16-split tensor cores ----
// 128x128 block tile, 8 warps (64x32 each), BK=16 (one k16 step), double-buffered.
// smem holds k-pair-packed words: sA[buf][hi/lo][kp][m], sB[buf][hi/lo][kp][n].
#define GLD 136

__global__ __launch_bounds__(256, 1) void gemm_bf16s(
    const float* __restrict__ A, const float* __restrict__ B, float* __restrict__ C,
    int M, int N, int K, int lda, int ldb, int ldc)
{
    __shared__ uint32_t sA[2][2][8 * GLD];
    __shared__ uint32_t sB[2][2][8 * GLD];

    const int tid = threadIdx.x, lane = tid & 31, warp = tid >> 5;
    const int grp = lane >> 2, qid = lane & 3;
    const int wm = (warp & 1) * 64, wn = (warp >> 1) * 32;
    const size_t row0 = (size_t)blockIdx.y * 128, col0 = (size_t)blockIdx.x * 128;

    float acc[4][4][4];
#pragma unroll
    for (int mt = 0; mt < 4; mt++)
#pragma unroll
        for (int nt = 0; nt < 4; nt++)
#pragma unroll
            for (int i = 0; i < 4; i++) acc[mt][nt][i] = 0.0f;

    const int ar  = tid >> 2;          // 0..63 (second row ar+64)
    const int ak4 = (tid & 3) << 2;    // 0,4,8,12
    const int bkp = tid >> 5;          // 0..7 (k-pair row)
    const int bn4 = (tid & 31) << 2;   // 0..124

    const float* Ag  = A + (row0 + ar) * lda + ak4;
    const float* Ag2 = A + (row0 + ar + 64) * lda + ak4;
    const float* Bg  = B + col0 + bn4;

    float4 a0r, a1r, b0r, b1r;
    a0r = *(const float4*)(Ag);
    a1r = *(const float4*)(Ag2);
    b0r = *(const float4*)(Bg + (size_t)(2 * bkp) * ldb);
    b1r = *(const float4*)(Bg + (size_t)(2 * bkp + 1) * ldb);

    int buf = 0;
    {   // store iter 0
        uint32_t h, l;
        int kp0 = ak4 >> 1;
        split2(a0r.x, a0r.y, h, l); sA[buf][0][kp0 * GLD + ar] = h;       sA[buf][1][kp0 * GLD + ar] = l;
        split2(a0r.z, a0r.w, h, l); sA[buf][0][(kp0 + 1) * GLD + ar] = h; sA[buf][1][(kp0 + 1) * GLD + ar] = l;
        split2(a1r.x, a1r.y, h, l); sA[buf][0][kp0 * GLD + ar + 64] = h;       sA[buf][1][kp0 * GLD + ar + 64] = l;
        split2(a1r.z, a1r.w, h, l); sA[buf][0][(kp0 + 1) * GLD + ar + 64] = h; sA[buf][1][(kp0 + 1) * GLD + ar + 64] = l;
        uint32_t hb[4], lb[4];
        split2(b0r.x, b1r.x, hb[0], lb[0]);
        split2(b0r.y, b1r.y, hb[1], lb[1]);
        split2(b0r.z, b1r.z, hb[2], lb[2]);
        split2(b0r.w, b1r.w, hb[3], lb[3]);
        *(uint4*)&sB[buf][0][bkp * GLD + bn4] = make_uint4(hb[0], hb[1], hb[2], hb[3]);
        *(uint4*)&sB[buf][1][bkp * GLD + bn4] = make_uint4(lb[0], lb[1], lb[2], lb[3]);
    }
    __syncthreads();

    const int NI = K >> 4;
    for (int it = 0; it < NI; it++) {
        if (it + 1 < NI) {
            int k0 = (it + 1) << 4;
            a0r = *(const float4*)(Ag + k0);
            a1r = *(const float4*)(Ag2 + k0);
            b0r = *(const float4*)(Bg + (size_t)(k0 + 2 * bkp) * ldb);
            b1r = *(const float4*)(Bg + (size_t)(k0 + 2 * bkp + 1) * ldb);
        }

        // compute this buffer (one k16 step)
        uint32_t ah[4][4], al[4][4], bh[4][2], bl[4][2];
#pragma unroll
        for (int mt = 0; mt < 4; mt++) {
            int m = wm + mt * 16 + grp;
            ah[mt][0] = sA[buf][0][qid * GLD + m];
            ah[mt][1] = sA[buf][0][qid * GLD + m + 8];
            ah[mt][2] = sA[buf][0][(qid + 4) * GLD + m];
            ah[mt][3] = sA[buf][0][(qid + 4) * GLD + m + 8];
            al[mt][0] = sA[buf][1][qid * GLD + m];
            al[mt][1] = sA[buf][1][qid * GLD + m + 8];
            al[mt][2] = sA[buf][1][(qid + 4) * GLD + m];
            al[mt][3] = sA[buf][1][(qid + 4) * GLD + m + 8];
        }
#pragma unroll
        for (int nt = 0; nt < 4; nt++) {
            int n = wn + nt * 8 + grp;
            bh[nt][0] = sB[buf][0][qid * GLD + n];
            bh[nt][1] = sB[buf][0][(qid + 4) * GLD + n];
            bl[nt][0] = sB[buf][1][qid * GLD + n];
            bl[nt][1] = sB[buf][1][(qid + 4) * GLD + n];
        }
#pragma unroll
        for (int mt = 0; mt < 4; mt++)
#pragma unroll
            for (int nt = 0; nt < 4; nt++) {
                mma16(acc[mt][nt], ah[mt], bh[nt]);
                mma16(acc[mt][nt], ah[mt], bl[nt]);
                mma16(acc[mt][nt], al[mt], bh[nt]);
            }

        if (it + 1 < NI) {
            buf ^= 1;
            uint32_t h, l;
            int kp0 = ak4 >> 1;
            split2(a0r.x, a0r.y, h, l); sA[buf][0][kp0 * GLD + ar] = h;       sA[buf][1][kp0 * GLD + ar] = l;
            split2(a0r.z, a0r.w, h, l); sA[buf][0][(kp0 + 1) * GLD + ar] = h; sA[buf][1][(kp0 + 1) * GLD + ar] = l;
            split2(a1r.x, a1r.y, h, l); sA[buf][0][kp0 * GLD + ar + 64] = h;       sA[buf][1][kp0 * GLD + ar + 64] = l;
            split2(a1r.z, a1r.w, h, l); sA[buf][0][(kp0 + 1) * GLD + ar + 64] = h; sA[buf][1][(kp0 + 1) * GLD + ar + 64] = l;
            uint32_t hb[4], lb[4];
            split2(b0r.x, b1r.x, hb[0], lb[0]);
            split2(b0r.y, b1r.y, hb[1], lb[1]);
            split2(b0r.z, b1r.z, hb[2], lb[2]);
            split2(b0r.w, b1r.w, hb[3], lb[3]);
            *(uint4*)&sB[buf][0][bkp * GLD + bn4] = make_uint4(hb[0], hb[1], hb[2], hb[3]);
            *(uint4*)&sB[buf][1][bkp * GLD + bn4] = make_uint4(lb[0], lb[1], lb[2], lb[3]);
            __syncthreads();
        }
    }

    // epilogue: c0,c1 -> (row, 2qid), c2,c3 -> (row+8, 2qid)
#pragma unroll
    for (int mt = 0; mt < 4; mt++) {
        size_t r = row0 + wm + mt * 16 + grp;
#pragma unroll
        for (int nt = 0; nt < 4; nt++) {
            size_t c = col0 + wn + nt * 8 + 2 * qid;
            *(float2*)(C + r * ldc + c)       = make_float2(acc[mt][nt][0], acc[mt][nt][1]);
            *(float2*)(C + (r + 8) * ldc + c) = make_float2(acc[mt][nt][2], acc[mt][nt][3]);
        }
    }
}

// ---------------- build Q/K/V: concat quirk + RoPE + scale-fold ----------------
__global__ __launch_bounds__(256) void build_qkv(
    const float* __restrict__ qn, const float* __restrict__ qr,
    const float* __restrict__ kn, const float* __restrict__ kr,
    const float* __restrict__ vf,
    float* __restrict__ Q, float* __restrict__ K, float* __restrict__ V)
{
    const int t = blockIdx.x;           // token 0..4095
    const int b = t / SS, s = t % SS;
    const float qscale = 0.08838834764831845f; // 1/sqrt(128)

    for (int idx = threadIdx.x; idx < NH * HD; idx += blockDim.x) {
        int h = idx / HD, d = idx % HD;
        size_t o = (((size_t)(b * NH + h)) * SS + s) * HD + d;

        V[o] = vf[(size_t)t * 2048 + h * 128 + d];

        float qv, kv;
        if (d < 64) {
            int c = h * 128 + d;
            if (c < 1024) { qv = qn[(size_t)t * 1024 + c];        kv = kn[(size_t)t * 1024 + c]; }
            else          { qv = qr[(size_t)t * 1024 + c - 1024]; kv = kr[(size_t)t * 1024 + c - 1024]; }
        } else {
            int j  = d - 64;
            int jj = (j < 32) ? j : j - 32;
            int c1 = h * 128 + 64 + jj;
            int c2 = c1 + 32;
            float r1q, r2q, r1k, r2k;
            if (c1 < 1024) {
                r1q = qn[(size_t)t * 1024 + c1]; r2q = qn[(size_t)t * 1024 + c2];
                r1k = kn[(size_t)t * 1024 + c1]; r2k = kn[(size_t)t * 1024 + c2];
            } else {
                r1q = qr[(size_t)t * 1024 + c1 - 1024]; r2q = qr[(size_t)t * 1024 + c2 - 1024];
                r1k = kr[(size_t)t * 1024 + c1 - 1024]; r2k = kr[(size_t)t * 1024 + c2 - 1024];
            }
            float invf = 1.0f / powf(10000.0f, (float)(2 * jj) / 64.0f);
            float ang = (float)s * invf;
            float cs = cosf(ang), sn = sinf(ang);
            if (j < 32) { qv = r1q * cs - r2q * sn; kv = r1k * cs - r2k * sn; }
            else        { qv = r1q * sn + r2q * cs; kv = r1k * sn + r2k * cs; }
        }
        Q[o] = qv * qscale;
        K[o] = kv;
    }
}

// ---------------- flash attention on tensor cores (bf16-split) ----------------
// BM=128 (8 warps x 16 rows), BN=64, D=128. All operands hi/lo split.
#define QLD 68    // 64 packed-d words + pad
#define VLD 136   // 128 d cols + pad
#define PLD 36    // 32 packed-kv words + pad

#define ATT_SMEM_WORDS (2*128*QLD + 2*64*QLD + 2*32*VLD + 2*128*PLD)
#define ATT_SMEM_BYTES (ATT_SMEM_WORDS * 4)

__global__ __launch_bounds__(256, 1) void attn_mma(
    const float* __restrict__ Qg, const float* __restrict__ Kg,
    const float* __restrict__ Vg, float* __restrict__ ctx)
{
    extern __shared__ uint32_t smw[];
    uint32_t* Qh = smw;
    uint32_t* Ql = Qh + 128 * QLD;
    uint32_t* Kh = Ql + 128 * QLD;
    uint32_t* Kl = Kh + 64 * QLD;
    uint32_t* Vh = Kl + 64 * QLD;
    uint32_t* Vl = Vh + 32 * VLD;
    uint32_t* Ph = Vl + 32 * VLD;
    uint32_t* Pl = Ph + 128 * PLD;

    const int tid = threadIdx.x, lane = tid & 31, warp = tid >> 5;
    const int grp = lane >> 2, qid = lane & 3;
    const int bh = blockIdx.y;
    const int q0 = blockIdx.x << 7;
    const size_t base = (size_t)bh * SS * HD;
    const int r0 = warp * 16;

    // load Q tile 128x128 -> packed hi/lo
#pragma unroll
    for (int i = 0; i < 16; i++) {
        int idx = tid + i * 256;
        int r = idx >> 5, c4 = (idx & 31) << 2;
        float4 v = *(const float4*)(Qg + base + (size_t)(q0 + r) * HD + c4);
        uint32_t h0, l0, h1, l1;
        split2(v.x, v.y, h0, l0);
        split2(v.z, v.w, h1, l1);
        int w = r * QLD + (c4 >> 1);
        *(uint2*)&Qh[w] = make_uint2(h0, h1);
        *(uint2*)&Ql[w] = make_uint2(l0, l1);
    }

    float m0 = -1e30f, m1 = -1e30f, l0s = 0.0f, l1s = 0.0f;
    float o[16][4];
#pragma unroll
    for (int t = 0; t < 16; t++)
#pragma unroll
        for (int i = 0; i < 4; i++) o[t][i] = 0.0f;

    for (int kv0 = 0; kv0 < SS; kv0 += 64) {
        __syncthreads();   // prior PV reads of Vh/Vl done
        // K tile 64x128
#pragma unroll
        for (int i = 0; i < 8; i++) {
            int idx = tid + i * 256;
            int r = idx >> 5, c4 = (idx & 31) << 2;
            float4 v = *(const float4*)(Kg + base + (size_t)(kv0 + r) * HD + c4);
            uint32_t h0, l0, h1, l1;
            split2(v.x, v.y, h0, l0);
            split2(v.z, v.w, h1, l1);
            int w = r * QLD + (c4 >> 1);
            *(uint2*)&Kh[w] = make_uint2(h0, h1);
            *(uint2*)&Kl[w] = make_uint2(l0, l1);
        }
        // V tile 64x128, packed along kv pairs
#pragma unroll
        for (int i = 0; i < 4; i++) {
            int kvp = (tid >> 5) + i * 8;      // 0..31
            int c4 = (tid & 31) << 2;
            float4 v0 = *(const float4*)(Vg + base + (size_t)(kv0 + 2 * kvp) * HD + c4);
            float4 v1 = *(const float4*)(Vg + base + (size_t)(kv0 + 2 * kvp + 1) * HD + c4);
            uint32_t hb[4], lb[4];
            split2(v0.x, v1.x, hb[0], lb[0]);
            split2(v0.y, v1.y, hb[1], lb[1]);
            split2(v0.z, v1.z, hb[2], lb[2]);
            split2(v0.w, v1.w, hb[3], lb[3]);
            *(uint4*)&Vh[kvp * VLD + c4] = make_uint4(hb[0], hb[1], hb[2], hb[3]);
            *(uint4*)&Vl[kvp * VLD + c4] = make_uint4(lb[0], lb[1], lb[2], lb[3]);
        }
        __syncthreads();

        // ---- S = Q K^T (rows r0..r0+15 of this warp, all 64 kv) ----
        float s[8][4];
#pragma unroll
        for (int nt = 0; nt < 8; nt++)
#pragma unroll
            for (int i = 0; i < 4; i++) s[nt][i] = 0.0f;

#pragma unroll
        for (int ks = 0; ks < 8; ks++) {
            int kp = ks * 8;
            uint32_t ah[4], al[4];
            ah[0] = Qh[(r0 + grp) * QLD + kp + qid];
            ah[1] = Qh[(r0 + grp + 8) * QLD + kp + qid];
            ah[2] = Qh[(r0 + grp) * QLD + kp + qid + 4];
            ah[3] = Qh[(r0 + grp + 8) * QLD + kp + qid + 4];
            al[0] = Ql[(r0 + grp) * QLD + kp + qid];
            al[1] = Ql[(r0 + grp + 8) * QLD + kp + qid];
            al[2] = Ql[(r0 + grp) * QLD + kp + qid + 4];
            al[3] = Ql[(r0 + grp + 8) * QLD + kp + qid + 4];
#pragma unroll
            for (int nt = 0; nt < 8; nt++) {
                uint32_t b2h[2], b2l[2];
                b2h[0] = Kh[(nt * 8 + grp) * QLD + kp + qid];
                b2h[1] = Kh[(nt * 8 + grp) * QLD + kp + qid + 4];
                b2l[0] = Kl[(nt * 8 + grp) * QLD + kp + qid];
                b2l[1] = Kl[(nt * 8 + grp) * QLD + kp + qid + 4];
                mma16(s[nt], ah, b2h);
                mma16(s[nt], ah, b2l);
                mma16(s[nt], al, b2h);
            }
        }

        // ---- online softmax (rows: a = r0+grp, b = r0+grp+8) ----
        float mxa = -1e30f, mxb = -1e30f;
#pragma unroll
        for (int nt = 0; nt < 8; nt++) {
            mxa = fmaxf(mxa, fmaxf(s[nt][0], s[nt][1]));
            mxb = fmaxf(mxb, fmaxf(s[nt][2], s[nt][3]));
        }
        mxa = fmaxf(mxa, __shfl_xor_sync(0xffffffffu, mxa, 1));
        mxa = fmaxf(mxa, __shfl_xor_sync(0xffffffffu, mxa, 2));
        mxb = fmaxf(mxb, __shfl_xor_sync(0xffffffffu, mxb, 1));
        mxb = fmaxf(mxb, __shfl_xor_sync(0xffffffffu, mxb, 2));
        float mna = fmaxf(m0, mxa), mnb = fmaxf(m1, mxb);
        float ca = __expf(m0 - mna), cb = __expf(m1 - mnb);
        float rsa = 0.0f, rsb = 0.0f;
#pragma unroll
        for (int nt = 0; nt < 8; nt++) {
            s[nt][0] = __expf(s[nt][0] - mna);
            s[nt][1] = __expf(s[nt][1] - mna);
            s[nt][2] = __expf(s[nt][2] - mnb);
            s[nt][3] = __expf(s[nt][3] - mnb);
            rsa += s[nt][0] + s[nt][1];
            rsb += s[nt][2] + s[nt][3];
        }
        rsa += __shfl_xor_sync(0xffffffffu, rsa, 1);
        rsa += __shfl_xor_sync(0xffffffffu, rsa, 2);
        rsb += __shfl_xor_sync(0xffffffffu, rsb, 1);
        rsb += __shfl_xor_sync(0xffffffffu, rsb, 2);
        l0s = l0s * ca + rsa;
        l1s = l1s * cb + rsb;
        m0 = mna; m1 = mnb;
#pragma unroll
        for (int t = 0; t < 16; t++) {
            o[t][0] *= ca; o[t][1] *= ca;
            o[t][2] *= cb; o[t][3] *= cb;
        }

        // ---- stage P (packed kv pairs), own-warp rows only ----
#pragma unroll
        for (int nt = 0; nt < 8; nt++) {
            uint32_t h, l;
            split2(s[nt][0], s[nt][1], h, l);
            Ph[(r0 + grp) * PLD + 4 * nt + qid] = h;
            Pl[(r0 + grp) * PLD + 4 * nt + qid] = l;
            split2(s[nt][2], s[nt][3], h, l);
            Ph[(r0 + grp + 8) * PLD + 4 * nt + qid] = h;
            Pl[(r0 + grp + 8) * PLD + 4 * nt + qid] = l;
        }
        __syncwarp();

        // ---- O += P @ V ----
#pragma unroll
        for (int ks = 0; ks < 4; ks++) {
            int kp = ks * 8;
            uint32_t ah[4], al[4];
            ah[0] = Ph[(r0 + grp) * PLD + kp + qid];
            ah[1] = Ph[(r0 + grp + 8) * PLD + kp + qid];
            ah[2] = Ph[(r0 + grp) * PLD + kp + qid + 4];
            ah[3] = Ph[(r0 + grp + 8) * PLD + kp + qid + 4];
            al[0] = Pl[(r0 + grp) * PLD + kp + qid];
            al[1] = Pl[(r0 + grp + 8) * PLD + kp + qid];
            al[2] = Pl[(r0 + grp) * PLD + kp + qid + 4];
            al[3] = Pl[(r0 + grp + 8) * PLD + kp + qid + 4];
#pragma unroll
            for (int nt = 0; nt < 16; nt++) {
                uint32_t b2h[2], b2l[2];
                b2h[0] = Vh[(kp + qid) * VLD + nt * 8 + grp];
                b2h[1] = Vh[(kp + qid + 4) * VLD + nt * 8 + grp];
                b2l[0] = Vl[(kp + qid) * VLD + nt * 8 + grp];
                b2l[1] = Vl[(kp + qid + 4) * VLD + nt * 8 + grp];
                mma16(o[nt], ah, b2h);
                mma16(o[nt], ah, b2l);
                mma16(o[nt], al, b2h);
            }
        }
    }

    // ---- epilogue: normalize and write ctx [token][2048] ----
    float ia = 1.0f / l0s, ib = 1.0f / l1s;
    const int b = bh >> 4, h = bh & 15;
    const size_t ta = (size_t)b * SS + q0 + r0 + grp;
    const size_t tb = ta + 8;
#pragma unroll
    for (int nt = 0; nt < 16; nt++) {
        size_t c = (size_t)h * 128 + nt * 8 + 2 * qid;
        *(float2*)(ctx + ta * 2048 + c) = make_float2(o[nt][0] * ia, o[nt][1] * ia);
        *(float2*)(ctx + tb * 2048 + c) = make_float2(o[nt][2] * ib, o[nt][3] * ib);
    }
}

// ---------------- launch ----------------
extern "C" void kernel_launch(void* const* d_in, const int* in_sizes, int n_in,
                              void* d_out, int out_size)
{
    const float* x        = (const float*)d_in[0];
    const float* W_comp   = (const float*)d_in[1];
    const float* W_q_dec  = (const float*)d_in[2];
    const float* W_k_dec  = (const float*)d_in[3];
    const float* W_v_dec  = (const float*)d_in[4];
    const float* W_rope_q = (const float*)d_in[5];
    const float* W_rope_k = (const float*)d_in[6];
    const float* W_out    = (const float*)d_in[7];
    float* out = (float*)d_out;

    float *comp, *qr, *kr, *qn, *kn, *vf, *Q, *K, *V, *ctx;
    cudaGetSymbolAddress((void**)&comp, g_comp);
    cudaGetSymbolAddress((void**)&qr,   g_qr);
    cudaGetSymbolAddress((void**)&kr,   g_kr);
    cudaGetSymbolAddress((void**)&qn,   g_qn);
    cudaGetSymbolAddress((void**)&kn,   g_kn);
    cudaGetSymbolAddress((void**)&vf,   g_vf);
    cudaGetSymbolAddress((void**)&Q,    g_Q);
    cudaGetSymbolAddress((void**)&K,    g_K);
    cudaGetSymbolAddress((void**)&V,    g_V);
    cudaGetSymbolAddress((void**)&ctx,  g_ctx);

    cudaFuncSetAttribute(attn_mma, cudaFuncAttributeMaxDynamicSharedMemorySize, ATT_SMEM_BYTES);

    dim3 thr(256);
    // compressed = x @ W_comp            [4096,2048]@[2048,512]
    gemm_bf16s<<<dim3(4, 32), thr>>>(x, W_comp, comp, MR, 512, 2048, 2048, 512, 512);
    // q_rope = x @ W_rope_q              [4096,2048]@[2048,1024]
    gemm_bf16s<<<dim3(8, 32), thr>>>(x, W_rope_q, qr, MR, 1024, 2048, 2048, 1024, 1024);
    // k_rope = x @ W_rope_k
    gemm_bf16s<<<dim3(8, 32), thr>>>(x, W_rope_k, kr, MR, 1024, 2048, 2048, 1024, 1024);
    // q_no_rope = c_qk @ W_q_dec         [4096,256 (lda=512)]@[256,1024]
    gemm_bf16s<<<dim3(8, 32), thr>>>(comp, W_q_dec, qn, MR, 1024, 256, 512, 1024, 1024);
    // k_no_rope = c_qk @ W_k_dec
    gemm_bf16s<<<dim3(8, 32), thr>>>(comp, W_k_dec, kn, MR, 1024, 256, 512, 1024, 1024);
    // v = c_v @ W_v_dec                  offset +256 into each compressed row
    gemm_bf16s<<<dim3(16, 32), thr>>>(comp + 256, W_v_dec, vf, MR, 2048, 256, 512, 2048, 2048);
    // assemble Q/K/V with RoPE quirk (Q pre-scaled by 1/sqrt(128))
    build_qkv<<<MR, 256>>>(qn, qr, kn, kr, vf, Q, K, V);
    // flash attention -> ctx [4096, 2048]
    attn_mma<<<dim3(SS / 128, BB * NH), thr, ATT_SMEM_BYTES>>>(Q, K, V, ctx);
    // out = ctx @ W_out                  [4096,2048]@[2048,2048]
    gemm_bf16s<<<dim3(16, 32), thr>>>(ctx, W_out, out, MR, 2048, 2048, 2048, 2048, 2048);
}

// round 4
// speedup vs baseline: 1.0737x; 1.0737x over previous
#include <cuda_runtime.h>
#include <cuda_bf16.h>
#include <math.h>
#include <stdint.h>

#define BB 2
#define SS 2048
#define NH 16
#define HD 128
#define MR (BB*SS)

// ---------------- scratch ----------------
__device__ float g_comp[MR*512];
__device__ float g_qr[MR*1024];
__device__ float g_kr[MR*1024];
__device__ float g_qn[MR*1024];
__device__ float g_kn[MR*1024];
__device__ float g_vf[MR*2048];
__device__ float g_V[(size_t)BB*NH*SS*HD];
__device__ float g_ctx[(size_t)MR*2048];
// packed bf16x2 hi/lo operand buffers for attention
__device__ uint32_t g_Qph[(size_t)32*SS*64], g_Qpl[(size_t)32*SS*64];
__device__ uint32_t g_Kph[(size_t)32*SS*64], g_Kpl[(size_t)32*SS*64];
__device__ uint32_t g_Vph[(size_t)32*(SS/2)*128], g_Vpl[(size_t)32*(SS/2)*128];

// ---------------- helpers ----------------
__device__ __forceinline__ void split2(float f0, float f1, uint32_t& hi, uint32_t& lo) {
    __nv_bfloat162 h = __floats2bfloat162_rn(f0, f1);
    float r0 = f0 - __bfloat162float(h.x);
    float r1 = f1 - __bfloat162float(h.y);
    __nv_bfloat162 l = __floats2bfloat162_rn(r0, r1);
    hi = *reinterpret_cast<uint32_t*>(&h);
    lo = *reinterpret_cast<uint32_t*>(&l);
}

__device__ __forceinline__ void mma16(float* c, const uint32_t* a, const uint32_t* b) {
    asm volatile(
        "mma.sync.aligned.m16n8k16.row.col.f32.bf16.bf16.f32 "
        "{%0,%1,%2,%3},{%4,%5,%6,%7},{%8,%9},{%0,%1,%2,%3};"
        : "+f"(c[0]), "+f"(c[1]), "+f"(c[2]), "+f"(c[3])
        : "r"(a[0]), "r"(a[1]), "r"(a[2]), "r"(a[3]), "r"(b[0]), "r"(b[1]));
}

__device__ __forceinline__ uint32_t smem_u32(const void* p) {
    uint32_t a;
    asm("{ .reg .u64 t; cvta.to.shared.u64 t, %1; cvt.u32.u64 %0, t; }" : "=r"(a) : "l"(p));
    return a;
}
__device__ __forceinline__ void cpa16(uint32_t dst, const void* src) {
    asm volatile("cp.async.cg.shared.global [%0], [%1], 16;" :: "r"(dst), "l"(src));
}
#define CPA_COMMIT() asm volatile("cp.async.commit_group;" ::: "memory")
#define CPA_WAIT1()  asm volatile("cp.async.wait_group 1;" ::: "memory")

// ---------------- SGEMM on tensor cores (bf16 3-term split) — unchanged ----------------
#define GLD 136
__global__ __launch_bounds__(256, 1) void gemm_bf16s(
    const float* __restrict__ A, const float* __restrict__ B, float* __restrict__ C,
    int M, int N, int K, int lda, int ldb, int ldc)
{
    __shared__ uint32_t sA[2][2][8 * GLD];
    __shared__ uint32_t sB[2][2][8 * GLD];
    const int tid = threadIdx.x, lane = tid & 31, warp = tid >> 5;
    const int grp = lane >> 2, qid = lane & 3;
    const int wm = (warp & 1) * 64, wn = (warp >> 1) * 32;
    const size_t row0 = (size_t)blockIdx.y * 128, col0 = (size_t)blockIdx.x * 128;

    float acc[4][4][4];
#pragma unroll
    for (int mt = 0; mt < 4; mt++)
#pragma unroll
        for (int nt = 0; nt < 4; nt++)
#pragma unroll
            for (int i = 0; i < 4; i++) acc[mt][nt][i] = 0.0f;

    const int ar = tid >> 2, ak4 = (tid & 3) << 2;
    const int bkp = tid >> 5, bn4 = (tid & 31) << 2;
    const float* Ag  = A + (row0 + ar) * lda + ak4;
    const float* Ag2 = A + (row0 + ar + 64) * lda + ak4;
    const float* Bg  = B + col0 + bn4;

    float4 a0r = *(const float4*)(Ag);
    float4 a1r = *(const float4*)(Ag2);
    float4 b0r = *(const float4*)(Bg + (size_t)(2 * bkp) * ldb);
    float4 b1r = *(const float4*)(Bg + (size_t)(2 * bkp + 1) * ldb);

    int buf = 0;
    {
        uint32_t h, l;
        int kp0 = ak4 >> 1;
        split2(a0r.x, a0r.y, h, l); sA[buf][0][kp0 * GLD + ar] = h;       sA[buf][1][kp0 * GLD + ar] = l;
        split2(a0r.z, a0r.w, h, l); sA[buf][0][(kp0 + 1) * GLD + ar] = h; sA[buf][1][(kp0 + 1) * GLD + ar] = l;
        split2(a1r.x, a1r.y, h, l); sA[buf][0][kp0 * GLD + ar + 64] = h;       sA[buf][1][kp0 * GLD + ar + 64] = l;
        split2(a1r.z, a1r.w, h, l); sA[buf][0][(kp0 + 1) * GLD + ar + 64] = h; sA[buf][1][(kp0 + 1) * GLD + ar + 64] = l;
        uint32_t hb[4], lb[4];
        split2(b0r.x, b1r.x, hb[0], lb[0]);
        split2(b0r.y, b1r.y, hb[1], lb[1]);
        split2(b0r.z, b1r.z, hb[2], lb[2]);
        split2(b0r.w, b1r.w, hb[3], lb[3]);
        *(uint4*)&sB[buf][0][bkp * GLD + bn4] = make_uint4(hb[0], hb[1], hb[2], hb[3]);
        *(uint4*)&sB[buf][1][bkp * GLD + bn4] = make_uint4(lb[0], lb[1], lb[2], lb[3]);
    }
    __syncthreads();

    const int NI = K >> 4;
    for (int it = 0; it < NI; it++) {
        if (it + 1 < NI) {
            int k0 = (it + 1) << 4;
            a0r = *(const float4*)(Ag + k0);
            a1r = *(const float4*)(Ag2 + k0);
            b0r = *(const float4*)(Bg + (size_t)(k0 + 2 * bkp) * ldb);
            b1r = *(const float4*)(Bg + (size_t)(k0 + 2 * bkp + 1) * ldb);
        }
        uint32_t ah[4][4], al[4][4], bh[4][2], bl[4][2];
#pragma unroll
        for (int mt = 0; mt < 4; mt++) {
            int m = wm + mt * 16 + grp;
            ah[mt][0] = sA[buf][0][qid * GLD + m];
            ah[mt][1] = sA[buf][0][qid * GLD + m + 8];
            ah[mt][2] = sA[buf][0][(qid + 4) * GLD + m];
            ah[mt][3] = sA[buf][0][(qid + 4) * GLD + m + 8];
            al[mt][0] = sA[buf][1][qid * GLD + m];
            al[mt][1] = sA[buf][1][qid * GLD + m + 8];
            al[mt][2] = sA[buf][1][(qid + 4) * GLD + m];
            al[mt][3] = sA[buf][1][(qid + 4) * GLD + m + 8];
        }
#pragma unroll
        for (int nt = 0; nt < 4; nt++) {
            int n = wn + nt * 8 + grp;
            bh[nt][0] = sB[buf][0][qid * GLD + n];
            bh[nt][1] = sB[buf][0][(qid + 4) * GLD + n];
            bl[nt][0] = sB[buf][1][qid * GLD + n];
            bl[nt][1] = sB[buf][1][(qid + 4) * GLD + n];
        }
#pragma unroll
        for (int mt = 0; mt < 4; mt++)
#pragma unroll
            for (int nt = 0; nt < 4; nt++) {
                mma16(acc[mt][nt], ah[mt], bh[nt]);
                mma16(acc[mt][nt], ah[mt], bl[nt]);
                mma16(acc[mt][nt], al[mt], bh[nt]);
            }
        if (it + 1 < NI) {
            buf ^= 1;
            uint32_t h, l;
            int kp0 = ak4 >> 1;
            split2(a0r.x, a0r.y, h, l); sA[buf][0][kp0 * GLD + ar] = h;       sA[buf][1][kp0 * GLD + ar] = l;
            split2(a0r.z, a0r.w, h, l); sA[buf][0][(kp0 + 1) * GLD + ar] = h; sA[buf][1][(kp0 + 1) * GLD + ar] = l;
            split2(a1r.x, a1r.y, h, l); sA[buf][0][kp0 * GLD + ar + 64] = h;       sA[buf][1][kp0 * GLD + ar + 64] = l;
            split2(a1r.z, a1r.w, h, l); sA[buf][0][(kp0 + 1) * GLD + ar + 64] = h; sA[buf][1][(kp0 + 1) * GLD + ar + 64] = l;
            uint32_t hb[4], lb[4];
            split2(b0r.x, b1r.x, hb[0], lb[0]);
            split2(b0r.y, b1r.y, hb[1], lb[1]);
            split2(b0r.z, b1r.z, hb[2], lb[2]);
            split2(b0r.w, b1r.w, hb[3], lb[3]);
            *(uint4*)&sB[buf][0][bkp * GLD + bn4] = make_uint4(hb[0], hb[1], hb[2], hb[3]);
            *(uint4*)&sB[buf][1][bkp * GLD + bn4] = make_uint4(lb[0], lb[1], lb[2], lb[3]);
            __syncthreads();
        }
    }
#pragma unroll
    for (int mt = 0; mt < 4; mt++) {
        size_t r = row0 + wm + mt * 16 + grp;
#pragma unroll
        for (int nt = 0; nt < 4; nt++) {
            size_t c = col0 + wn + nt * 8 + 2 * qid;
            *(float2*)(C + r * ldc + c)       = make_float2(acc[mt][nt][0], acc[mt][nt][1]);
            *(float2*)(C + (r + 8) * ldc + c) = make_float2(acc[mt][nt][2], acc[mt][nt][3]);
        }
    }
}

// ---------------- build Q/K (packed split) + V fp32 ----------------
__device__ __forceinline__ void qk_elem(
    const float* qn, const float* qr, const float* kn, const float* kr,
    int t, int s, int h, int d, float& qv, float& kv)
{
    if (d < 64) {
        int c = h * 128 + d;
        if (c < 1024) { qv = qn[(size_t)t * 1024 + c];        kv = kn[(size_t)t * 1024 + c]; }
        else          { qv = qr[(size_t)t * 1024 + c - 1024]; kv = kr[(size_t)t * 1024 + c - 1024]; }
    } else {
        int j  = d - 64;
        int jj = (j < 32) ? j : j - 32;
        int c1 = h * 128 + 64 + jj, c2 = c1 + 32;
        float r1q, r2q, r1k, r2k;
        if (c1 < 1024) {
            r1q = qn[(size_t)t * 1024 + c1]; r2q = qn[(size_t)t * 1024 + c2];
            r1k = kn[(size_t)t * 1024 + c1]; r2k = kn[(size_t)t * 1024 + c2];
        } else {
            r1q = qr[(size_t)t * 1024 + c1 - 1024]; r2q = qr[(size_t)t * 1024 + c2 - 1024];
            r1k = kr[(size_t)t * 1024 + c1 - 1024]; r2k = kr[(size_t)t * 1024 + c2 - 1024];
        }
        float invf = 1.0f / powf(10000.0f, (float)(2 * jj) / 64.0f);
        float ang = (float)s * invf;
        float cs = cosf(ang), sn = sinf(ang);
        if (j < 32) { qv = r1q * cs - r2q * sn; kv = r1k * cs - r2k * sn; }
        else        { qv = r1q * sn + r2q * cs; kv = r1k * sn + r2k * cs; }
    }
}

__global__ __launch_bounds__(256) void build_qkv2(
    const float* __restrict__ qn, const float* __restrict__ qr,
    const float* __restrict__ kn, const float* __restrict__ kr,
    const float* __restrict__ vf,
    uint32_t* __restrict__ Qh, uint32_t* __restrict__ Ql,
    uint32_t* __restrict__ Kh, uint32_t* __restrict__ Kl,
    float* __restrict__ V)
{
    const int t = blockIdx.x;
    const int b = t / SS, s = t % SS;
    const float qs = 0.08838834764831845f;
    for (int idx = threadIdx.x; idx < 1024; idx += 256) {
        int h = idx >> 6, w = idx & 63, d0 = 2 * w;
        float q0, k0, q1, k1;
        qk_elem(qn, qr, kn, kr, t, s, h, d0,     q0, k0);
        qk_elem(qn, qr, kn, kr, t, s, h, d0 + 1, q1, k1);
        size_t row = (size_t)(b * NH + h) * SS + s;
        float2 v = *(const float2*)(vf + (size_t)t * 2048 + h * 128 + d0);
        *(float2*)(V + row * 128 + d0) = v;
        uint32_t hh, ll;
        split2(q0 * qs, q1 * qs, hh, ll);
        Qh[row * 64 + w] = hh; Ql[row * 64 + w] = ll;
        split2(k0, k1, hh, ll);
        Kh[row * 64 + w] = hh; Kl[row * 64 + w] = ll;
    }
}

// pack V row-pairs: Vp[bh][p][d] = bf16x2(V[2p][d], V[2p+1][d]) hi/lo
__global__ __launch_bounds__(256) void pack_v(
    const float* __restrict__ V, uint32_t* __restrict__ Vh, uint32_t* __restrict__ Vl)
{
    size_t n = (size_t)32 * (SS / 2) * 128;
    for (size_t i = (size_t)blockIdx.x * blockDim.x + threadIdx.x; i < n;
         i += (size_t)gridDim.x * blockDim.x) {
        size_t p = i >> 7;
        int d = (int)(i & 127);
        float v0 = V[(p * 2) * 128 + d];
        float v1 = V[(p * 2 + 1) * 128 + d];
        uint32_t h, l;
        split2(v0, v1, h, l);
        Vh[i] = h; Vl[i] = l;
    }
}

// ---------------- flash attention v2: reg-resident Q, cp.async K/V, reg P ----
#define KLD 68
#define VLD 136
#define STGW (2*64*KLD + 2*32*VLD)       // 17408 words per stage
#define ATT2_SMEM_BYTES (2*STGW*4)       // 139264 B

__global__ __launch_bounds__(256, 1) void attn2(
    const uint32_t* __restrict__ Qph, const uint32_t* __restrict__ Qpl,
    const uint32_t* __restrict__ Kph, const uint32_t* __restrict__ Kpl,
    const uint32_t* __restrict__ Vph, const uint32_t* __restrict__ Vpl,
    float* __restrict__ ctx)
{
    extern __shared__ uint32_t sm2[];
    const uint32_t smb = smem_u32(sm2);
    const int tid = threadIdx.x, lane = tid & 31, warp = tid >> 5;
    const int grp = lane >> 2, qid = lane & 3;
    const int bh = blockIdx.y;
    const int q0 = blockIdx.x << 7;
    const int r0 = warp * 16;

    const uint32_t* Kb  = Kph + (size_t)bh * SS * 64;
    const uint32_t* Klb = Kpl + (size_t)bh * SS * 64;
    const uint32_t* Vb  = Vph + (size_t)bh * (SS / 2) * 128;
    const uint32_t* Vlb = Vpl + (size_t)bh * (SS / 2) * 128;

    // Q fragments resident in registers
    uint32_t qh[32], ql[32];
    {
        const uint32_t* ra = Qph + ((size_t)bh * SS + q0 + r0 + grp) * 64;
        const uint32_t* rb = ra + 8 * 64;
        const uint32_t* la = Qpl + ((size_t)bh * SS + q0 + r0 + grp) * 64;
        const uint32_t* lb = la + 8 * 64;
#pragma unroll
        for (int ks = 0; ks < 8; ks++) {
            qh[4 * ks + 0] = ra[8 * ks + qid];
            qh[4 * ks + 1] = rb[8 * ks + qid];
            qh[4 * ks + 2] = ra[8 * ks + qid + 4];
            qh[4 * ks + 3] = rb[8 * ks + qid + 4];
            ql[4 * ks + 0] = la[8 * ks + qid];
            ql[4 * ks + 1] = lb[8 * ks + qid];
            ql[4 * ks + 2] = la[8 * ks + qid + 4];
            ql[4 * ks + 3] = lb[8 * ks + qid + 4];
        }
    }

    const int j0 = tid, j1 = tid + 256, j2 = tid + 512, j3 = tid + 768;
#define ISSUE(stg, ti) do {                                                       \
    int kv0_ = (ti) << 6;                                                         \
    uint32_t sb = smb + (stg) * (STGW * 4);                                       \
    int js[4] = {j0, j1, j2, j3};                                                 \
    _Pragma("unroll")                                                             \
    for (int u = 0; u < 4; u++) {                                                 \
        int r = js[u] >> 4, c = (js[u] & 15) << 2;                                \
        cpa16(sb + (r * KLD + c) * 4,            Kb  + (size_t)(kv0_ + r) * 64 + c); \
        cpa16(sb + ((64 + r) * KLD + c) * 4,     Klb + (size_t)(kv0_ + r) * 64 + c); \
        int rv = js[u] >> 5, cv = (js[u] & 31) << 2;                              \
        cpa16(sb + (128 * KLD + rv * VLD + cv) * 4,                               \
              Vb  + ((size_t)(kv0_ >> 1) + rv) * 128 + cv);                       \
        cpa16(sb + (128 * KLD + 32 * VLD + rv * VLD + cv) * 4,                    \
              Vlb + ((size_t)(kv0_ >> 1) + rv) * 128 + cv);                       \
    }                                                                             \
} while (0)

    ISSUE(0, 0); CPA_COMMIT();
    ISSUE(1, 1); CPA_COMMIT();

    float m0 = -1e30f, m1 = -1e30f, l0s = 0.0f, l1s = 0.0f;
    float o[16][4];
#pragma unroll
    for (int t = 0; t < 16; t++)
#pragma unroll
        for (int i = 0; i < 4; i++) o[t][i] = 0.0f;

    const int NT = SS / 64;
    for (int it = 0; it < NT; it++) {
        int stg = it & 1;
        CPA_WAIT1();
        __syncthreads();
        const uint32_t* Kh_s = sm2 + stg * STGW;
        const uint32_t* Kl_s = Kh_s + 64 * KLD;
        const uint32_t* Vh_s = Kh_s + 128 * KLD;
        const uint32_t* Vl_s = Vh_s + 32 * VLD;

        // ---- S = Q K^T ----
        float s[8][4];
#pragma unroll
        for (int nt = 0; nt < 8; nt++)
#pragma unroll
            for (int i = 0; i < 4; i++) s[nt][i] = 0.0f;
#pragma unroll
        for (int ks = 0; ks < 8; ks++) {
#pragma unroll
            for (int nt = 0; nt < 8; nt++) {
                uint32_t bhw[2], blw[2];
                int rowk = (nt * 8 + grp) * KLD + 8 * ks + qid;
                bhw[0] = Kh_s[rowk];
                bhw[1] = Kh_s[rowk + 4];
                blw[0] = Kl_s[rowk];
                blw[1] = Kl_s[rowk + 4];
                mma16(s[nt], &qh[4 * ks], bhw);
                mma16(s[nt], &qh[4 * ks], blw);
                mma16(s[nt], &ql[4 * ks], bhw);
            }
        }

        // ---- online softmax ----
        float mxa = -1e30f, mxb = -1e30f;
#pragma unroll
        for (int nt = 0; nt < 8; nt++) {
            mxa = fmaxf(mxa, fmaxf(s[nt][0], s[nt][1]));
            mxb = fmaxf(mxb, fmaxf(s[nt][2], s[nt][3]));
        }
        mxa = fmaxf(mxa, __shfl_xor_sync(0xffffffffu, mxa, 1));
        mxa = fmaxf(mxa, __shfl_xor_sync(0xffffffffu, mxa, 2));
        mxb = fmaxf(mxb, __shfl_xor_sync(0xffffffffu, mxb, 1));
        mxb = fmaxf(mxb, __shfl_xor_sync(0xffffffffu, mxb, 2));
        float mna = fmaxf(m0, mxa), mnb = fmaxf(m1, mxb);
        float ca = __expf(m0 - mna), cb = __expf(m1 - mnb);
        float rsa = 0.0f, rsb = 0.0f;
#pragma unroll
        for (int nt = 0; nt < 8; nt++) {
            s[nt][0] = __expf(s[nt][0] - mna);
            s[nt][1] = __expf(s[nt][1] - mna);
            s[nt][2] = __expf(s[nt][2] - mnb);
            s[nt][3] = __expf(s[nt][3] - mnb);
            rsa += s[nt][0] + s[nt][1];
            rsb += s[nt][2] + s[nt][3];
        }
        rsa += __shfl_xor_sync(0xffffffffu, rsa, 1);
        rsa += __shfl_xor_sync(0xffffffffu, rsa, 2);
        rsb += __shfl_xor_sync(0xffffffffu, rsb, 1);
        rsb += __shfl_xor_sync(0xffffffffu, rsb, 2);
        l0s = l0s * ca + rsa;
        l1s = l1s * cb + rsb;
        m0 = mna; m1 = mnb;
#pragma unroll
        for (int t = 0; t < 16; t++) {
            o[t][0] *= ca; o[t][1] *= ca;
            o[t][2] *= cb; o[t][3] *= cb;
        }

        // ---- O += P V : P fragments built in registers from S fragments ----
#pragma unroll
        for (int ks = 0; ks < 4; ks++) {
            uint32_t ah[4], al[4];
            split2(s[2 * ks][0],     s[2 * ks][1],     ah[0], al[0]);
            split2(s[2 * ks][2],     s[2 * ks][3],     ah[1], al[1]);
            split2(s[2 * ks + 1][0], s[2 * ks + 1][1], ah[2], al[2]);
            split2(s[2 * ks + 1][2], s[2 * ks + 1][3], ah[3], al[3]);
#pragma unroll
            for (int nt = 0; nt < 16; nt++) {
                uint32_t bhw[2], blw[2];
                int c = nt * 8 + grp;
                bhw[0] = Vh_s[(8 * ks + qid) * VLD + c];
                bhw[1] = Vh_s[(8 * ks + qid + 4) * VLD + c];
                blw[0] = Vl_s[(8 * ks + qid) * VLD + c];
                blw[1] = Vl_s[(8 * ks + qid + 4) * VLD + c];
                mma16(o[nt], ah, bhw);
                mma16(o[nt], ah, blw);
                mma16(o[nt], al, bhw);
            }
        }

        __syncthreads();
        if (it + 2 < NT) ISSUE(stg, it + 2);
        CPA_COMMIT();
    }

    float ia = 1.0f / l0s, ib = 1.0f / l1s;
    const int b = bh >> 4, h = bh & 15;
    const size_t ta = (size_t)b * SS + q0 + r0 + grp;
    const size_t tb = ta + 8;
#pragma unroll
    for (int nt = 0; nt < 16; nt++) {
        size_t c = (size_t)h * 128 + nt * 8 + 2 * qid;
        *(float2*)(ctx + ta * 2048 + c) = make_float2(o[nt][0] * ia, o[nt][1] * ia);
        *(float2*)(ctx + tb * 2048 + c) = make_float2(o[nt][2] * ib, o[nt][3] * ib);
    }
}

// ---------------- launch ----------------
extern "C" void kernel_launch(void* const* d_in, const int* in_sizes, int n_in,
                              void* d_out, int out_size)
{
    const float* x        = (const float*)d_in[0];
    const float* W_comp   = (const float*)d_in[1];
    const float* W_q_dec  = (const float*)d_in[2];
    const float* W_k_dec  = (const float*)d_in[3];
    const float* W_v_dec  = (const float*)d_in[4];
    const float* W_rope_q = (const float*)d_in[5];
    const float* W_rope_k = (const float*)d_in[6];
    const float* W_out    = (const float*)d_in[7];
    float* out = (float*)d_out;

    float *comp, *qr, *kr, *qn, *kn, *vf, *V, *ctx;
    uint32_t *Qph, *Qpl, *Kph, *Kpl, *Vph, *Vpl;
    cudaGetSymbolAddress((void**)&comp, g_comp);
    cudaGetSymbolAddress((void**)&qr,   g_qr);
    cudaGetSymbolAddress((void**)&kr,   g_kr);
    cudaGetSymbolAddress((void**)&qn,   g_qn);
    cudaGetSymbolAddress((void**)&kn,   g_kn);
    cudaGetSymbolAddress((void**)&vf,   g_vf);
    cudaGetSymbolAddress((void**)&V,    g_V);
    cudaGetSymbolAddress((void**)&ctx,  g_ctx);
    cudaGetSymbolAddress((void**)&Qph,  g_Qph);
    cudaGetSymbolAddress((void**)&Qpl,  g_Qpl);
    cudaGetSymbolAddress((void**)&Kph,  g_Kph);
    cudaGetSymbolAddress((void**)&Kpl,  g_Kpl);
    cudaGetSymbolAddress((void**)&Vph,  g_Vph);
    cudaGetSymbolAddress((void**)&Vpl,  g_Vpl);

    cudaFuncSetAttribute(attn2, cudaFuncAttributeMaxDynamicSharedMemorySize, ATT2_SMEM_BYTES);

    dim3 thr(256);
    gemm_bf16s<<<dim3(4, 32), thr>>>(x, W_comp, comp, MR, 512, 2048, 2048, 512, 512);
    gemm_bf16s<<<dim3(8, 32), thr>>>(x, W_rope_q, qr, MR, 1024, 2048, 2048, 1024, 1024);
    gemm_bf16s<<<dim3(8, 32), thr>>>(x, W_rope_k, kr, MR, 1024, 2048, 2048, 1024, 1024);
    gemm_bf16s<<<dim3(8, 32), thr>>>(comp, W_q_dec, qn, MR, 1024, 256, 512, 1024, 1024);
    gemm_bf16s<<<dim3(8, 32), thr>>>(comp, W_k_dec, kn, MR, 1024, 256, 512, 1024, 1024);
    gemm_bf16s<<<dim3(16, 32), thr>>>(comp + 256, W_v_dec, vf, MR, 2048, 256, 512, 2048, 2048);
    build_qkv2<<<MR, 256>>>(qn, qr, kn, kr, vf, Qph, Qpl, Kph, Kpl, V);
    pack_v<<<4096, 256>>>(V, Vph, Vpl);
    attn2<<<dim3(SS / 128, BB * NH), thr, ATT2_SMEM_BYTES>>>(Qph, Qpl, Kph, Kpl, Vph, Vpl, ctx);
    gemm_bf16s<<<dim3(16, 32), thr>>>(ctx, W_out, out, MR, 2048, 2048, 2048, 2048, 2048);
}

// round 6
// speedup vs baseline: 1.0803x; 1.0062x over previous
#include <cuda_runtime.h>
#include <cuda_bf16.h>
#include <math.h>
#include <stdint.h>

#define BB 2
#define SS 2048
#define NH 16
#define HD 128
#define MR (BB*SS)

// ---------------- scratch ----------------
__device__ float g_comp[MR*512];
__device__ float g_qr[MR*1024];
__device__ float g_kr[MR*1024];
__device__ float g_qn[MR*1024];
__device__ float g_kn[MR*1024];
__device__ float g_vf[MR*2048];
__device__ float g_ctx[(size_t)MR*2048];
// packed bf16x2 operands (fragment-pair-permuted word order)
__device__ uint32_t g_Qph[(size_t)32*SS*64], g_Qpl[(size_t)32*SS*64];
__device__ uint32_t g_Kph[(size_t)32*SS*64], g_Kpl[(size_t)32*SS*64];
// V transposed: [bh][d 0..127][kv-pair 0..1023] (permuted within 8-word blocks)
__device__ uint32_t g_Vtph[(size_t)32*128*1024], g_Vtpl[(size_t)32*128*1024];

// ---------------- helpers ----------------
__device__ __forceinline__ void split2(float f0, float f1, uint32_t& hi, uint32_t& lo) {
    __nv_bfloat162 h = __floats2bfloat162_rn(f0, f1);
    float r0 = f0 - __bfloat162float(h.x);
    float r1 = f1 - __bfloat162float(h.y);
    __nv_bfloat162 l = __floats2bfloat162_rn(r0, r1);
    hi = *reinterpret_cast<uint32_t*>(&h);
    lo = *reinterpret_cast<uint32_t*>(&l);
}
__device__ __forceinline__ void mma16(float* c, const uint32_t* a, const uint32_t* b) {
    asm volatile(
        "mma.sync.aligned.m16n8k16.row.col.f32.bf16.bf16.f32 "
        "{%0,%1,%2,%3},{%4,%5,%6,%7},{%8,%9},{%0,%1,%2,%3};"
        : "+f"(c[0]), "+f"(c[1]), "+f"(c[2]), "+f"(c[3])
        : "r"(a[0]), "r"(a[1]), "r"(a[2]), "r"(a[3]), "r"(b[0]), "r"(b[1]));
}
__device__ __forceinline__ uint32_t smem_u32(const void* p) {
    uint32_t a;
    asm("{ .reg .u64 t; cvta.to.shared.u64 t, %1; cvt.u32.u64 %0, t; }" : "=r"(a) : "l"(p));
    return a;
}
__device__ __forceinline__ void cpa16(uint32_t dst, const void* src) {
    asm volatile("cp.async.cg.shared.global [%0], [%1], 16;" :: "r"(dst), "l"(src));
}
#define CPA_COMMIT() asm volatile("cp.async.commit_group;" ::: "memory")
#define CPA_WAIT1()  asm volatile("cp.async.wait_group 1;" ::: "memory")

// word permutation inside each 8-word k-block: logical j -> (j&3)*2 + (j>>2)
__device__ __host__ __forceinline__ int bperm(int w) {
    return (w & ~7) | (((w & 3) << 1) | ((w >> 2) & 1));
}

// ---------------- SGEMM on tensor cores (bf16 3-term split) — proven ----------------
#define GLD 136
__global__ __launch_bounds__(256, 1) void gemm_bf16s(
    const float* __restrict__ A, const float* __restrict__ B, float* __restrict__ C,
    int M, int N, int K, int lda, int ldb, int ldc)
{
    __shared__ uint32_t sA[2][2][8 * GLD];
    __shared__ uint32_t sB[2][2][8 * GLD];
    const int tid = threadIdx.x, lane = tid & 31, warp = tid >> 5;
    const int grp = lane >> 2, qid = lane & 3;
    const int wm = (warp & 1) * 64, wn = (warp >> 1) * 32;
    const size_t row0 = (size_t)blockIdx.y * 128, col0 = (size_t)blockIdx.x * 128;

    float acc[4][4][4];
#pragma unroll
    for (int mt = 0; mt < 4; mt++)
#pragma unroll
        for (int nt = 0; nt < 4; nt++)
#pragma unroll
            for (int i = 0; i < 4; i++) acc[mt][nt][i] = 0.0f;

    const int ar = tid >> 2, ak4 = (tid & 3) << 2;
    const int bkp = tid >> 5, bn4 = (tid & 31) << 2;
    const float* Ag  = A + (row0 + ar) * lda + ak4;
    const float* Ag2 = A + (row0 + ar + 64) * lda + ak4;
    const float* Bg  = B + col0 + bn4;

    float4 a0r = *(const float4*)(Ag);
    float4 a1r = *(const float4*)(Ag2);
    float4 b0r = *(const float4*)(Bg + (size_t)(2 * bkp) * ldb);
    float4 b1r = *(const float4*)(Bg + (size_t)(2 * bkp + 1) * ldb);

    int buf = 0;
    {
        uint32_t h, l;
        int kp0 = ak4 >> 1;
        split2(a0r.x, a0r.y, h, l); sA[buf][0][kp0 * GLD + ar] = h;       sA[buf][1][kp0 * GLD + ar] = l;
        split2(a0r.z, a0r.w, h, l); sA[buf][0][(kp0 + 1) * GLD + ar] = h; sA[buf][1][(kp0 + 1) * GLD + ar] = l;
        split2(a1r.x, a1r.y, h, l); sA[buf][0][kp0 * GLD + ar + 64] = h;       sA[buf][1][kp0 * GLD + ar + 64] = l;
        split2(a1r.z, a1r.w, h, l); sA[buf][0][(kp0 + 1) * GLD + ar + 64] = h; sA[buf][1][(kp0 + 1) * GLD + ar + 64] = l;
        uint32_t hb[4], lb[4];
        split2(b0r.x, b1r.x, hb[0], lb[0]);
        split2(b0r.y, b1r.y, hb[1], lb[1]);
        split2(b0r.z, b1r.z, hb[2], lb[2]);
        split2(b0r.w, b1r.w, hb[3], lb[3]);
        *(uint4*)&sB[buf][0][bkp * GLD + bn4] = make_uint4(hb[0], hb[1], hb[2], hb[3]);
        *(uint4*)&sB[buf][1][bkp * GLD + bn4] = make_uint4(lb[0], lb[1], lb[2], lb[3]);
    }
    __syncthreads();

    const int NI = K >> 4;
    for (int it = 0; it < NI; it++) {
        if (it + 1 < NI) {
            int k0 = (it + 1) << 4;
            a0r = *(const float4*)(Ag + k0);
            a1r = *(const float4*)(Ag2 + k0);
            b0r = *(const float4*)(Bg + (size_t)(k0 + 2 * bkp) * ldb);
            b1r = *(const float4*)(Bg + (size_t)(k0 + 2 * bkp + 1) * ldb);
        }
        uint32_t ah[4][4], al[4][4], bh[4][2], bl[4][2];
#pragma unroll
        for (int mt = 0; mt < 4; mt++) {
            int m = wm + mt * 16 + grp;
            ah[mt][0] = sA[buf][0][qid * GLD + m];
            ah[mt][1] = sA[buf][0][qid * GLD + m + 8];
            ah[mt][2] = sA[buf][0][(qid + 4) * GLD + m];
            ah[mt][3] = sA[buf][0][(qid + 4) * GLD + m + 8];
            al[mt][0] = sA[buf][1][qid * GLD + m];
            al[mt][1] = sA[buf][1][qid * GLD + m + 8];
            al[mt][2] = sA[buf][1][(qid + 4) * GLD + m];
            al[mt][3] = sA[buf][1][(qid + 4) * GLD + m + 8];
        }
#pragma unroll
        for (int nt = 0; nt < 4; nt++) {
            int n = wn + nt * 8 + grp;
            bh[nt][0] = sB[buf][0][qid * GLD + n];
            bh[nt][1] = sB[buf][0][(qid + 4) * GLD + n];
            bl[nt][0] = sB[buf][1][qid * GLD + n];
            bl[nt][1] = sB[buf][1][(qid + 4) * GLD + n];
        }
#pragma unroll
        for (int mt = 0; mt < 4; mt++)
#pragma unroll
            for (int nt = 0; nt < 4; nt++) {
                mma16(acc[mt][nt], ah[mt], bh[nt]);
                mma16(acc[mt][nt], ah[mt], bl[nt]);
                mma16(acc[mt][nt], al[mt], bh[nt]);
            }
        if (it + 1 < NI) {
            buf ^= 1;
            uint32_t h, l;
            int kp0 = ak4 >> 1;
            split2(a0r.x, a0r.y, h, l); sA[buf][0][kp0 * GLD + ar] = h;       sA[buf][1][kp0 * GLD + ar] = l;
            split2(a0r.z, a0r.w, h, l); sA[buf][0][(kp0 + 1) * GLD + ar] = h; sA[buf][1][(kp0 + 1) * GLD + ar] = l;
            split2(a1r.x, a1r.y, h, l); sA[buf][0][kp0 * GLD + ar + 64] = h;       sA[buf][1][kp0 * GLD + ar + 64] = l;
            split2(a1r.z, a1r.w, h, l); sA[buf][0][(kp0 + 1) * GLD + ar + 64] = h; sA[buf][1][(kp0 + 1) * GLD + ar + 64] = l;
            uint32_t hb[4], lb[4];
            split2(b0r.x, b1r.x, hb[0], lb[0]);
            split2(b0r.y, b1r.y, hb[1], lb[1]);
            split2(b0r.z, b1r.z, hb[2], lb[2]);
            split2(b0r.w, b1r.w, hb[3], lb[3]);
            *(uint4*)&sB[buf][0][bkp * GLD + bn4] = make_uint4(hb[0], hb[1], hb[2], hb[3]);
            *(uint4*)&sB[buf][1][bkp * GLD + bn4] = make_uint4(lb[0], lb[1], lb[2], lb[3]);
            __syncthreads();
        }
    }
#pragma unroll
    for (int mt = 0; mt < 4; mt++) {
        size_t r = row0 + wm + mt * 16 + grp;
#pragma unroll
        for (int nt = 0; nt < 4; nt++) {
            size_t c = col0 + wn + nt * 8 + 2 * qid;
            *(float2*)(C + r * ldc + c)       = make_float2(acc[mt][nt][0], acc[mt][nt][1]);
            *(float2*)(C + (r + 8) * ldc + c) = make_float2(acc[mt][nt][2], acc[mt][nt][3]);
        }
    }
}

// ---------------- build packed Q/K (RoPE quirk + scale fold, permuted) -------
__device__ __forceinline__ void qk_elem(
    const float* qn, const float* qr, const float* kn, const float* kr,
    int t, int s, int h, int d, float& qv, float& kv)
{
    if (d < 64) {
        int c = h * 128 + d;
        if (c < 1024) { qv = qn[(size_t)t * 1024 + c];        kv = kn[(size_t)t * 1024 + c]; }
        else          { qv = qr[(size_t)t * 1024 + c - 1024]; kv = kr[(size_t)t * 1024 + c - 1024]; }
    } else {
        int j  = d - 64;
        int jj = (j < 32) ? j : j - 32;
        int c1 = h * 128 + 64 + jj, c2 = c1 + 32;
        float r1q, r2q, r1k, r2k;
        if (c1 < 1024) {
            r1q = qn[(size_t)t * 1024 + c1]; r2q = qn[(size_t)t * 1024 + c2];
            r1k = kn[(size_t)t * 1024 + c1]; r2k = kn[(size_t)t * 1024 + c2];
        } else {
            r1q = qr[(size_t)t * 1024 + c1 - 1024]; r2q = qr[(size_t)t * 1024 + c2 - 1024];
            r1k = kr[(size_t)t * 1024 + c1 - 1024]; r2k = kr[(size_t)t * 1024 + c2 - 1024];
        }
        float invf = 1.0f / powf(10000.0f, (float)(2 * jj) / 64.0f);
        float ang = (float)s * invf;
        float cs = cosf(ang), sn = sinf(ang);
        if (j < 32) { qv = r1q * cs - r2q * sn; kv = r1k * cs - r2k * sn; }
        else        { qv = r1q * sn + r2q * cs; kv = r1k * sn + r2k * cs; }
    }
}

__global__ __launch_bounds__(256) void build_qk(
    const float* __restrict__ qn, const float* __restrict__ qr,
    const float* __restrict__ kn, const float* __restrict__ kr,
    uint32_t* __restrict__ Qh, uint32_t* __restrict__ Ql,
    uint32_t* __restrict__ Kh, uint32_t* __restrict__ Kl)
{
    const int t = blockIdx.x;
    const int b = t / SS, s = t % SS;
    const float qs = 0.08838834764831845f;
    for (int idx = threadIdx.x; idx < 1024; idx += 256) {
        int h = idx >> 6, w = idx & 63, d0 = 2 * w;
        float q0, k0, q1, k1;
        qk_elem(qn, qr, kn, kr, t, s, h, d0,     q0, k0);
        qk_elem(qn, qr, kn, kr, t, s, h, d0 + 1, q1, k1);
        size_t row = (size_t)(b * NH + h) * SS + s;
        int wp = bperm(w);
        uint32_t hh, ll;
        split2(q0 * qs, q1 * qs, hh, ll);
        Qh[row * 64 + wp] = hh; Ql[row * 64 + wp] = ll;
        split2(k0, k1, hh, ll);
        Kh[row * 64 + wp] = hh; Kl[row * 64 + wp] = ll;
    }
}

// ---------------- V transpose+pack: vf[t][2048] -> Vt[bh][d][pair] (permuted)
__global__ __launch_bounds__(256) void pack_vt(
    const float* __restrict__ vf, uint32_t* __restrict__ Vh, uint32_t* __restrict__ Vl)
{
    __shared__ float sv[64][129];
    const int bh = blockIdx.y, b = bh >> 4, h = bh & 15;
    const int kv0 = blockIdx.x * 64;
    const int tid = threadIdx.x;
    // load 64 kv rows x 128 d (coalesced along d)
#pragma unroll
    for (int i = 0; i < 32; i++) {
        int idx = tid + i * 256;
        int r = idx >> 7, d = idx & 127;
        sv[r][d] = vf[((size_t)(b * SS + kv0 + r)) * 2048 + h * 128 + d];
    }
    __syncthreads();
    // write 128 d rows x 32 pair-words (permuted)
    const int d = tid >> 1, jh = (tid & 1) * 16;
    uint32_t* oh = Vh + ((size_t)bh * 128 + d) * 1024 + (kv0 >> 1);
    uint32_t* ol = Vl + ((size_t)bh * 128 + d) * 1024 + (kv0 >> 1);
#pragma unroll
    for (int j = jh; j < jh + 16; j++) {
        uint32_t hh, ll;
        split2(sv[2 * j][d], sv[2 * j + 1][d], hh, ll);
        int wp = bperm(j);
        oh[wp] = hh; ol[wp] = ll;
    }
}

// ---------------- flash attention v4 (mma.sync, no-max softmax) --------------
// stage layout (bytes): KH 64x72w=18432 | KL 18432 | VH 128x40w=20480 | VL 20480
#define KH_O(s) ((s)*77824 + 0)
#define KL_O(s) ((s)*77824 + 18432)
#define VH_O(s) ((s)*77824 + 36864)
#define VL_O(s) ((s)*77824 + 57344)
#define ATT4_SMEM (2*77824)

__global__ __launch_bounds__(256, 1) void attn4(
    const uint32_t* __restrict__ Qph, const uint32_t* __restrict__ Qpl,
    const uint32_t* __restrict__ Kph, const uint32_t* __restrict__ Kpl,
    const uint32_t* __restrict__ Vtph, const uint32_t* __restrict__ Vtpl,
    float* __restrict__ ctx)
{
    extern __shared__ __align__(16) char sm4[];
    const uint32_t smb = smem_u32(sm4);
    const uint32_t* smw = (const uint32_t*)sm4;
    const int tid = threadIdx.x, lane = tid & 31, warp = tid >> 5;
    const int grp = lane >> 2, qid = lane & 3;
    const int bh = blockIdx.y;
    const int q0 = blockIdx.x << 7;
    const int r0 = warp * 16;

    const char* Khg = (const char*)(Kph + (size_t)bh * SS * 64);
    const char* Klg = (const char*)(Kpl + (size_t)bh * SS * 64);
    const char* Vhg = (const char*)(Vtph + (size_t)bh * 128 * 1024);
    const char* Vlg = (const char*)(Vtpl + (size_t)bh * 128 * 1024);

    // Q fragments in registers (uint2 loads thanks to permuted layout)
    uint32_t qh[32], ql[32];
    {
        const uint2* ra = (const uint2*)(Qph + ((size_t)bh * SS + q0 + r0 + grp) * 64);
        const uint2* rb = (const uint2*)(Qph + ((size_t)bh * SS + q0 + r0 + grp + 8) * 64);
        const uint2* la = (const uint2*)(Qpl + ((size_t)bh * SS + q0 + r0 + grp) * 64);
        const uint2* lb = (const uint2*)(Qpl + ((size_t)bh * SS + q0 + r0 + grp + 8) * 64);
#pragma unroll
        for (int ks = 0; ks < 8; ks++) {
            uint2 xa = ra[4 * ks + qid], xb = rb[4 * ks + qid];
            uint2 ya = la[4 * ks + qid], yb = lb[4 * ks + qid];
            qh[4 * ks + 0] = xa.x; qh[4 * ks + 1] = xb.x;
            qh[4 * ks + 2] = xa.y; qh[4 * ks + 3] = xb.y;
            ql[4 * ks + 0] = ya.x; ql[4 * ks + 1] = yb.x;
            ql[4 * ks + 2] = ya.y; ql[4 * ks + 3] = yb.y;
        }
    }

#define ISSUE4(stg, ti) do {                                                       \
    int kv0_ = (ti) << 6;                                                          \
    uint32_t sb = smb;                                                             \
    _Pragma("unroll")                                                              \
    for (int u = 0; u < 4; u++) {                                                  \
        int c = tid + 256 * u;                                                     \
        int rk = c >> 4, ck = (c & 15) << 4;                                       \
        cpa16(sb + KH_O(stg) + rk * 288 + ck, Khg + (size_t)(kv0_ + rk) * 256 + ck); \
        cpa16(sb + KL_O(stg) + rk * 288 + ck, Klg + (size_t)(kv0_ + rk) * 256 + ck); \
        int rv = c >> 3, cv = (c & 7) << 4;                                        \
        cpa16(sb + VH_O(stg) + rv * 160 + cv, Vhg + (size_t)rv * 4096 + kv0_ * 2 + cv); \
        cpa16(sb + VL_O(stg) + rv * 160 + cv, Vlg + (size_t)rv * 4096 + kv0_ * 2 + cv); \
    }                                                                              \
} while (0)

    ISSUE4(0, 0); CPA_COMMIT();
    ISSUE4(1, 1); CPA_COMMIT();

    float la = 0.0f, lb2 = 0.0f;
    float o[16][4];
#pragma unroll
    for (int t = 0; t < 16; t++)
#pragma unroll
        for (int i = 0; i < 4; i++) o[t][i] = 0.0f;

    const int NT = SS / 64;
    for (int it = 0; it < NT; it++) {
        int stg = it & 1;
        CPA_WAIT1();
        __syncthreads();
        const uint32_t* Kh_s = smw + (KH_O(stg) >> 2);
        const uint32_t* Kl_s = smw + (KL_O(stg) >> 2);
        const uint32_t* Vh_s = smw + (VH_O(stg) >> 2);
        const uint32_t* Vl_s = smw + (VL_O(stg) >> 2);

        // ---- S = Q K^T ----
        float s[8][4];
#pragma unroll
        for (int nt = 0; nt < 8; nt++)
#pragma unroll
            for (int i = 0; i < 4; i++) s[nt][i] = 0.0f;
#pragma unroll
        for (int ks = 0; ks < 8; ks++) {
#pragma unroll
            for (int nt = 0; nt < 8; nt++) {
                uint2 b2h = *(const uint2*)(Kh_s + (nt * 8 + grp) * 72 + ks * 8 + 2 * qid);
                uint2 b2l = *(const uint2*)(Kl_s + (nt * 8 + grp) * 72 + ks * 8 + 2 * qid);
                uint32_t bhw[2] = {b2h.x, b2h.y}, blw[2] = {b2l.x, b2l.y};
                mma16(s[nt], &qh[4 * ks], bhw);
                mma16(s[nt], &qh[4 * ks], blw);
                mma16(s[nt], &ql[4 * ks], bhw);
            }
        }

        // ---- exp (no max subtraction; scores bounded) + deferred sums ----
        float pa0 = 0.0f, pa1 = 0.0f, pb0 = 0.0f, pb1 = 0.0f;
#pragma unroll
        for (int nt = 0; nt < 8; nt++) {
            s[nt][0] = __expf(s[nt][0]);
            s[nt][1] = __expf(s[nt][1]);
            s[nt][2] = __expf(s[nt][2]);
            s[nt][3] = __expf(s[nt][3]);
            pa0 += s[nt][0]; pa1 += s[nt][1];
            pb0 += s[nt][2]; pb1 += s[nt][3];
        }
        la  += pa0 + pa1;
        lb2 += pb0 + pb1;

        // ---- O += P V (P fragments split in registers) ----
#pragma unroll
        for (int ks = 0; ks < 4; ks++) {
            uint32_t ah[4], al[4];
            split2(s[2 * ks][0],     s[2 * ks][1],     ah[0], al[0]);
            split2(s[2 * ks][2],     s[2 * ks][3],     ah[1], al[1]);
            split2(s[2 * ks + 1][0], s[2 * ks + 1][1], ah[2], al[2]);
            split2(s[2 * ks + 1][2], s[2 * ks + 1][3], ah[3], al[3]);
#pragma unroll
            for (int nt = 0; nt < 16; nt++) {
                uint2 b2h = *(const uint2*)(Vh_s + (nt * 8 + grp) * 40 + ks * 8 + 2 * qid);
                uint2 b2l = *(const uint2*)(Vl_s + (nt * 8 + grp) * 40 + ks * 8 + 2 * qid);
                uint32_t bhw[2] = {b2h.x, b2h.y}, blw[2] = {b2l.x, b2l.y};
                mma16(o[nt], ah, bhw);
                mma16(o[nt], ah, blw);
                mma16(o[nt], al, bhw);
            }
        }

        __syncthreads();
        if (it + 2 < NT) ISSUE4(stg, it + 2);
        CPA_COMMIT();
    }

    // final l reduction across the 4 qid lanes of each row group
    la  += __shfl_xor_sync(0xffffffffu, la, 1);
    la  += __shfl_xor_sync(0xffffffffu, la, 2);
    lb2 += __shfl_xor_sync(0xffffffffu, lb2, 1);
    lb2 += __shfl_xor_sync(0xffffffffu, lb2, 2);
    float ia = 1.0f / la, ib = 1.0f / lb2;

    const int b = bh >> 4, h = bh & 15;
    const size_t ta = (size_t)b * SS + q0 + r0 + grp;
    const size_t tb = ta + 8;
#pragma unroll
    for (int nt = 0; nt < 16; nt++) {
        size_t c = (size_t)h * 128 + nt * 8 + 2 * qid;
        *(float2*)(ctx + ta * 2048 + c) = make_float2(o[nt][0] * ia, o[nt][1] * ia);
        *(float2*)(ctx + tb * 2048 + c) = make_float2(o[nt][2] * ib, o[nt][3] * ib);
    }
}

// ---------------- launch ----------------
extern "C" void kernel_launch(void* const* d_in, const int* in_sizes, int n_in,
                              void* d_out, int out_size)
{
    const float* x        = (const float*)d_in[0];
    const float* W_comp   = (const float*)d_in[1];
    const float* W_q_dec  = (const float*)d_in[2];
    const float* W_k_dec  = (const float*)d_in[3];
    const float* W_v_dec  = (const float*)d_in[4];
    const float* W_rope_q = (const float*)d_in[5];
    const float* W_rope_k = (const float*)d_in[6];
    const float* W_out    = (const float*)d_in[7];
    float* out = (float*)d_out;

    float *comp, *qr, *kr, *qn, *kn, *vf, *ctx;
    uint32_t *Qph, *Qpl, *Kph, *Kpl, *Vtph, *Vtpl;
    cudaGetSymbolAddress((void**)&comp, g_comp);
    cudaGetSymbolAddress((void**)&qr,   g_qr);
    cudaGetSymbolAddress((void**)&kr,   g_kr);
    cudaGetSymbolAddress((void**)&qn,   g_qn);
    cudaGetSymbolAddress((void**)&kn,   g_kn);
    cudaGetSymbolAddress((void**)&vf,   g_vf);
    cudaGetSymbolAddress((void**)&ctx,  g_ctx);
    cudaGetSymbolAddress((void**)&Qph,  g_Qph);
    cudaGetSymbolAddress((void**)&Qpl,  g_Qpl);
    cudaGetSymbolAddress((void**)&Kph,  g_Kph);
    cudaGetSymbolAddress((void**)&Kpl,  g_Kpl);
    cudaGetSymbolAddress((void**)&Vtph, g_Vtph);
    cudaGetSymbolAddress((void**)&Vtpl, g_Vtpl);

    cudaFuncSetAttribute(attn4, cudaFuncAttributeMaxDynamicSharedMemorySize, ATT4_SMEM);

    dim3 thr(256);
    gemm_bf16s<<<dim3(4, 32), thr>>>(x, W_comp, comp, MR, 512, 2048, 2048, 512, 512);
    gemm_bf16s<<<dim3(8, 32), thr>>>(x, W_rope_q, qr, MR, 1024, 2048, 2048, 1024, 1024);
    gemm_bf16s<<<dim3(8, 32), thr>>>(x, W_rope_k, kr, MR, 1024, 2048, 2048, 1024, 1024);
    gemm_bf16s<<<dim3(8, 32), thr>>>(comp, W_q_dec, qn, MR, 1024, 256, 512, 1024, 1024);
    gemm_bf16s<<<dim3(8, 32), thr>>>(comp, W_k_dec, kn, MR, 1024, 256, 512, 1024, 1024);
    gemm_bf16s<<<dim3(16, 32), thr>>>(comp + 256, W_v_dec, vf, MR, 2048, 256, 512, 2048, 2048);
    build_qk<<<MR, 256>>>(qn, qr, kn, kr, Qph, Qpl, Kph, Kpl);
    pack_vt<<<dim3(SS / 64, BB * NH), 256>>>(vf, Vtph, Vtpl);
    attn4<<<dim3(SS / 128, BB * NH), thr, ATT4_SMEM>>>(Qph, Qpl, Kph, Kpl, Vtph, Vtpl, ctx);
    gemm_bf16s<<<dim3(16, 32), thr>>>(ctx, W_out, out, MR, 2048, 2048, 2048, 2048, 2048);
}